// round 7
// baseline (speedup 1.0000x reference)
#include <cuda_runtime.h>
#include <math.h>

// ---------------- problem constants ----------------
#define NB   8
#define NC   256
#define NG   4
#define CG   64
#define NHH  4
#define WW   128
#define HWSZ 16384        // 128*128
#define LP   1024         // pooled spatial (32*32)
#define DH   256          // LP/NH
#define DV   4096         // HW/NH

// ---------------- scratch ----------------
__device__ float g_xp [NB*NC*LP];
__device__ float g_q  [NB*NC*LP];
__device__ float g_k  [NB*NC*LP];
__device__ float g_v  [NB*NC*HWSZ];
__device__ float g_sim[NB*NHH*256*256];
__device__ float g_msim[NB*NHH*256*256];
__device__ float g_bias[NHH*256*256];
__device__ float g_invq[NB*NHH*256];
__device__ float g_invk[NB*NHH*256];
__device__ float g_projw[256*256];
__device__ float g_scw [256*256];

// ---------------- helpers ----------------
__device__ __forceinline__ float warpRedSum(float v){
#pragma unroll
    for (int o = 16; o > 0; o >>= 1) v += __shfl_xor_sync(0xffffffffu, v, o);
    return v;
}
__device__ __forceinline__ float warpRedMax(float v){
#pragma unroll
    for (int o = 16; o > 0; o >>= 1) v = fmaxf(v, __shfl_xor_sync(0xffffffffu, v, o));
    return v;
}
__device__ __forceinline__ float warpRedMin(float v){
#pragma unroll
    for (int o = 16; o > 0; o >>= 1) v = fminf(v, __shfl_xor_sync(0xffffffffu, v, o));
    return v;
}
__device__ __forceinline__ unsigned f2tf(float f){
    unsigned u; asm("cvt.rna.tf32.f32 %0, %1;" : "=r"(u) : "f"(f)); return u;
}
__device__ __forceinline__ float roundtf(float f){ return __uint_as_float(f2tf(f)); }
__device__ __forceinline__ void mma8(float* c, unsigned a0, unsigned a1, unsigned a2, unsigned a3,
                                     unsigned b0, unsigned b1){
    asm volatile("mma.sync.aligned.m16n8k8.row.col.f32.tf32.tf32.f32 "
                 "{%0,%1,%2,%3},{%4,%5,%6,%7},{%8,%9},{%0,%1,%2,%3};"
                 : "+f"(c[0]), "+f"(c[1]), "+f"(c[2]), "+f"(c[3])
                 : "r"(a0), "r"(a1), "r"(a2), "r"(a3), "r"(b0), "r"(b1));
}
#define CP_ASYNC16(saddr, gptr) \
    asm volatile("cp.async.cg.shared.global [%0], [%1], 16;" :: "r"(saddr), "l"(gptr))
#define CP_ASYNC16Z(saddr, gptr, sz) \
    asm volatile("cp.async.cg.shared.global [%0], [%1], 16, %2;" :: "r"(saddr), "l"(gptr), "r"(sz))
#define CP_COMMIT  asm volatile("cp.async.commit_group;")
#define CP_WAIT0   asm volatile("cp.async.wait_group 0;")
#define CP_WAIT1   asm volatile("cp.async.wait_group 1;")

// ---------------- K1: 4x4 maxpool ----------------
__global__ void k_maxpool(const float* __restrict__ xin, float* __restrict__ out){
    int idx = blockIdx.x * 256 + threadIdx.x;
    int pp = idx & 1023;
    int bc = idx >> 10;
    int ph = pp >> 5, pw = pp & 31;
    const float* xp = xin + (long)bc * HWSZ + (ph * 4) * WW + pw * 4;
    float m = -3.4e38f;
#pragma unroll
    for (int i = 0; i < 4; i++)
#pragma unroll
        for (int j = 0; j < 4; j++)
            m = fmaxf(m, xp[i * WW + j]);
    out[idx] = m;
}

// ---------------- K2: grouped 1x1 pw conv (q/k), output rounded to tf32 ----------------
__global__ void k_grouped_pw(const float* __restrict__ in, const float* __restrict__ w,
                             const float* __restrict__ bias, float* __restrict__ out, int L){
    __shared__ float wsT[64 * 64];
    __shared__ float xs[64][128];
    int g = blockIdx.y, b = blockIdx.z;
    int l0 = blockIdx.x * 128;
    int t = threadIdx.x;
    for (int idx = t; idx < 4096; idx += 128){
        int i = idx >> 6, j = idx & 63;
        wsT[j * 64 + i] = w[g * 4096 + idx];
    }
    const float* ip = in + ((long)(b * NC + g * CG)) * L + l0;
#pragma unroll 8
    for (int j = 0; j < 64; j++) xs[j][t] = ip[(long)j * L + t];
    __syncthreads();
    float acc[64];
#pragma unroll
    for (int i = 0; i < 64; i++) acc[i] = 0.f;
#pragma unroll 4
    for (int j = 0; j < 64; j++){
        float xv = xs[j][t];
        const float4* wr = (const float4*)(wsT + j * 64);
#pragma unroll
        for (int i4 = 0; i4 < 16; i4++){
            float4 wv = wr[i4];
            acc[i4*4+0] += wv.x * xv;
            acc[i4*4+1] += wv.y * xv;
            acc[i4*4+2] += wv.z * xv;
            acc[i4*4+3] += wv.w * xv;
        }
    }
    float* op = out + ((long)(b * NC + g * CG)) * L + l0;
#pragma unroll 8
    for (int i = 0; i < 64; i++)
        op[(long)i * L + t] = roundtf(acc[i] + bias[g * CG + i]);
}

// ---------------- K3: fused dw3x3+relu (chunked cp.async) + grouped pw (mma) ----------------
__device__ __forceinline__ void dw_issue_chunk(const float* __restrict__ xb, unsigned xs_u32,
                                               int ch, int y0, int t){
#pragma unroll
    for (int i = 0; i < 4; i++){
        int vid = t + i * 256;
        int cl = vid >> 7;
        int rem = vid & 127;
        int ry = rem >> 5, col4 = (rem & 31) * 4;
        int c = ch * 8 + cl;
        int row = y0 - 1 + ry;
        int ok = (row >= 0 && row <= 127);
        const float* src = xb + (long)c * HWSZ + (ok ? row : 0) * 128 + col4;
        unsigned dst = xs_u32 + (unsigned)(((c * 4 + ry) * 128 + col4) * 4);
        int sz = ok ? 16 : 0;
        CP_ASYNC16Z(dst, src, sz);
    }
    CP_COMMIT;
}

__global__ void __launch_bounds__(256)
k_dwpw(const float* __restrict__ x, const float* __restrict__ dw_w,
       const float* __restrict__ dw_b, const float* __restrict__ pw_w,
       const float* __restrict__ pw_b, float* __restrict__ vout){
    extern __shared__ float sm[];
    float*    xs  = sm;                        // 64ch * 4 rows * 128 = 32768 f
    unsigned* Bs  = (unsigned*)(sm + 32768);   // 64*260 = 16640
    unsigned* Asw = Bs + 16640;                // 64*68 = 4352
    __shared__ float sdw[576];
    __shared__ float sdb[64];

    int g = blockIdx.y, b = blockIdx.z;
    int p0 = blockIdx.x * 256;
    int t = threadIdx.x;
    int y0 = p0 >> 7;
    const float* xb = x + ((long)(b * NC + g * CG)) * HWSZ;
    unsigned xs_u32 = (unsigned)__cvta_generic_to_shared(xs);

    dw_issue_chunk(xb, xs_u32, 0, y0, t);

    // weights (plain loads, visible after first barrier)
    for (int idx = t; idx < 4096; idx += 256){
        int i = idx >> 6, j = idx & 63;
        Asw[i * 68 + j] = f2tf(pw_w[g * 4096 + idx]);
    }
    for (int idx = t; idx < 576; idx += 256) sdw[idx] = dw_w[g * 576 + idx];
    if (t < 64) sdb[t] = dw_b[g * 64 + t];

    int ly = 1 + (t >> 7);
    int xc = t & 127;

    for (int ch = 0; ch < 8; ch++){
        if (ch < 7){ dw_issue_chunk(xb, xs_u32, ch + 1, y0, t); CP_WAIT1; }
        else       { CP_WAIT0; }
        __syncthreads();
#pragma unroll
        for (int cl = 0; cl < 8; cl++){
            int c = ch * 8 + cl;
            float s = sdb[c];
            const float* xcb = xs + c * 512;
#pragma unroll
            for (int dy = 0; dy < 3; dy++){
                const float* xr = xcb + (ly + dy - 1) * 128;
#pragma unroll
                for (int dx = 0; dx < 3; dx++){
                    int xx = xc + dx - 1;
                    if (xx >= 0 && xx < 128) s += xr[xx] * sdw[c * 9 + dy * 3 + dx];
                }
            }
            Bs[c * 260 + t] = f2tf(fmaxf(s, 0.f));
        }
    }
    __syncthreads();

    int lane = t & 31, w = t >> 5, wm = w & 1, wn = w >> 1;
    int gq = lane >> 2, tg = lane & 3;
    float acc[2][8][4];
#pragma unroll
    for (int mt = 0; mt < 2; mt++)
#pragma unroll
        for (int nt = 0; nt < 8; nt++)
#pragma unroll
            for (int q = 0; q < 4; q++) acc[mt][nt][q] = 0.f;

#pragma unroll
    for (int ks = 0; ks < 8; ks++){
        unsigned af[2][4], bf[8][2];
        int c = ks * 8 + tg;
#pragma unroll
        for (int mt = 0; mt < 2; mt++){
            int r = wm * 32 + mt * 16 + gq;
            af[mt][0] = Asw[r * 68 + c];
            af[mt][1] = Asw[(r + 8) * 68 + c];
            af[mt][2] = Asw[r * 68 + c + 4];
            af[mt][3] = Asw[(r + 8) * 68 + c + 4];
        }
#pragma unroll
        for (int nt = 0; nt < 8; nt++){
            int cc = wn * 64 + nt * 8 + gq;
            bf[nt][0] = Bs[c * 260 + cc];
            bf[nt][1] = Bs[(c + 4) * 260 + cc];
        }
#pragma unroll
        for (int mt = 0; mt < 2; mt++)
#pragma unroll
            for (int nt = 0; nt < 8; nt++)
                mma8(acc[mt][nt], af[mt][0], af[mt][1], af[mt][2], af[mt][3],
                     bf[nt][0], bf[nt][1]);
    }

#pragma unroll
    for (int mt = 0; mt < 2; mt++){
        int rA = wm * 32 + mt * 16 + gq, rB = rA + 8;
        float bA = pw_b[g * 64 + rA], bB = pw_b[g * 64 + rB];
        float* oA = vout + ((long)(b * NC + g * 64 + rA)) * HWSZ + p0;
        float* oB = vout + ((long)(b * NC + g * 64 + rB)) * HWSZ + p0;
#pragma unroll
        for (int nt = 0; nt < 8; nt++){
            int col = wn * 64 + nt * 8 + tg * 2;
            *(float2*)&oA[col] = make_float2(roundtf(acc[mt][nt][0] + bA), roundtf(acc[mt][nt][1] + bA));
            *(float2*)&oB[col] = make_float2(roundtf(acc[mt][nt][2] + bB), roundtf(acc[mt][nt][3] + bB));
        }
    }
}

// ---------------- K4: row inverse norms of q,k heads ----------------
__global__ void k_rownorm(const float* __restrict__ q, const float* __restrict__ k,
                          float* __restrict__ invq, float* __restrict__ invk){
    int gw = (blockIdx.x * blockDim.x + threadIdx.x) >> 5;
    int lane = threadIdx.x & 31;
    int sel = gw >> 13;
    int r = gw & 8191;
    int b = r >> 10; int rem = r & 1023; int h = rem >> 8; int c = rem & 255;
    const float* src = (sel ? k : q) + (long)b * NC * LP + (long)c * LP + h * DH;
    float s = 0.f;
#pragma unroll
    for (int d = lane; d < DH; d += 32){ float v = src[d]; s += v * v; }
    s = warpRedSum(s);
    if (lane == 0){
        float inv = 1.f / fmaxf(sqrtf(s), 1e-12f);
        (sel ? invk : invq)[(b * NHH + h) * 256 + c] = inv;
    }
}

// ---------------- K4b: round proj_w and sc_w to tf32 ----------------
__global__ void k_roundw(const float* __restrict__ a, const float* __restrict__ b,
                         float* __restrict__ oa, float* __restrict__ ob){
    int i = blockIdx.x * 256 + threadIdx.x;
    oa[i] = roundtf(a[i]);
    ob[i] = roundtf(b[i]);
}

// ---------------- K5: CPB relative position bias ----------------
__global__ void k_cpb(const float* __restrict__ w1, const float* __restrict__ b1,
                      const float* __restrict__ w2, float* __restrict__ biasb){
    __shared__ float s1[64], sb1[64], s2[256];
    int t = threadIdx.x;
    if (t < 64){ s1[t] = w1[t]; sb1[t] = b1[t]; }
    s2[t] = w2[t];
    __syncthreads();
    int idx = blockIdx.x * 256 + t;
    int i = idx >> 8, j = idx & 255;
    float coords = (float)(j - i);
    float rel = coords * (8.0f / 255.0f);
    float sg = (rel > 0.f) ? 1.f : ((rel < 0.f) ? -1.f : 0.f);
    float f = sg * log2f(fabsf(rel) + 1.f) * (1.f / 3.f);
    float o0 = 0.f, o1 = 0.f, o2 = 0.f, o3 = 0.f;
#pragma unroll 8
    for (int h = 0; h < 64; h++){
        float hv = fmaxf(f * s1[h] + sb1[h], 0.f);
        o0 += hv * s2[h * 4 + 0];
        o1 += hv * s2[h * 4 + 1];
        o2 += hv * s2[h * 4 + 2];
        o3 += hv * s2[h * 4 + 3];
    }
    biasb[0 * 65536 + idx] = 1.f / (1.f + expf(-o0));
    biasb[1 * 65536 + idx] = 1.f / (1.f + expf(-o1));
    biasb[2 * 65536 + idx] = 1.f / (1.f + expf(-o2));
    biasb[3 * 65536 + idx] = 1.f / (1.f + expf(-o3));
}

// ---------------- K7: double softmax, warp per row, rounded store ----------------
__global__ void k_dsoftmax(float* __restrict__ simb){
    int row = blockIdx.x * 8 + (threadIdx.x >> 5);
    int lane = threadIdx.x & 31;
    float* p = simb + (long)row * 256;
    float v[8];
#pragma unroll
    for (int j = 0; j < 8; j++) v[j] = p[lane + 32 * j];
    float m = v[0];
#pragma unroll
    for (int j = 1; j < 8; j++) m = fmaxf(m, v[j]);
    m = warpRedMax(m);
    float s = 0.f;
#pragma unroll
    for (int j = 0; j < 8; j++){ v[j] = expf(v[j] - m); s += v[j]; }
    s = warpRedSum(s);
    float inv = 1.f / s;
    float mn = v[0];
#pragma unroll
    for (int j = 1; j < 8; j++) mn = fminf(mn, v[j]);
    mn = warpRedMin(mn);
    // softmax(1-p) == softmax(-p); exp(-v*inv + mn*inv) = exp((mn - v)*inv)
    float e2[8]; float s2 = 0.f;
#pragma unroll
    for (int j = 0; j < 8; j++){ e2[j] = expf((mn - v[j]) * inv); s2 += e2[j]; }
    s2 = warpRedSum(s2);
    float i2 = 1.f / s2;
#pragma unroll
    for (int j = 0; j < 8; j++) p[lane + 32 * j] = roundtf(e2[j] * i2);
}

// ---------------- tf32 async GEMM core: 128x128 tile, K=256, 3-stage cp.async ----------------
#define A_WORDS 4608   // 128*36
#define B_WORDS 4352   // 32*136

__device__ __forceinline__ void cpA(const float* __restrict__ Ab, long lda, int kt, int tid,
                                    unsigned as_u32){
#pragma unroll
    for (int i = 0; i < 4; i++){
        int vid = tid + i * 256;
        int r = vid >> 3, c4 = (vid & 7) << 2;
        CP_ASYNC16(as_u32 + (unsigned)((r * 36 + c4) * 4),
                   Ab + (long)r * lda + kt * 32 + c4);
    }
}
__device__ __forceinline__ void cpB(const float* __restrict__ Bb, long ldb, int kt, int tid,
                                    unsigned bs_u32){
#pragma unroll
    for (int i = 0; i < 4; i++){
        int vid = tid + i * 256;
        int kr = vid >> 5, n4 = (vid & 31) << 2;
        CP_ASYNC16(bs_u32 + (unsigned)((kr * 136 + n4) * 4),
                   Bb + (long)(kt * 32 + kr) * ldb + n4);
    }
}

__device__ __forceinline__ void compute_tile(const unsigned* As, const unsigned* Bs,
        float acc[4][4][4], int wm, int wn, int gq, int tg){
#pragma unroll
    for (int ks = 0; ks < 4; ks++){
        unsigned af[4][4], bf[4][2];
        int c = ks * 8 + tg;
#pragma unroll
        for (int mt = 0; mt < 4; mt++){
            int r = wm * 64 + mt * 16 + gq;
            af[mt][0] = As[r * 36 + c];
            af[mt][1] = As[(r + 8) * 36 + c];
            af[mt][2] = As[r * 36 + c + 4];
            af[mt][3] = As[(r + 8) * 36 + c + 4];
        }
#pragma unroll
        for (int nt = 0; nt < 4; nt++){
            int cc = wn * 32 + nt * 8 + gq;
            bf[nt][0] = Bs[c * 136 + cc];
            bf[nt][1] = Bs[(c + 4) * 136 + cc];
        }
#pragma unroll
        for (int mt = 0; mt < 4; mt++)
#pragma unroll
            for (int nt = 0; nt < 4; nt++)
                mma8(acc[mt][nt], af[mt][0], af[mt][1], af[mt][2], af[mt][3],
                     bf[nt][0], bf[nt][1]);
    }
}

__device__ __forceinline__ void gemm_async(const float* __restrict__ Ab, long lda,
        const float* __restrict__ Bb, long ldb,
        const unsigned* As, const unsigned* Bs, unsigned as0, unsigned bs0,
        float acc[4][4][4], int tid){
    int lane = tid & 31, w = tid >> 5, wm = w & 1, wn = w >> 1;
    int gq = lane >> 2, tg = lane & 3;
    cpA(Ab, lda, 0, tid, as0); cpB(Bb, ldb, 0, tid, bs0); CP_COMMIT;
    cpA(Ab, lda, 1, tid, as0 + A_WORDS * 4); cpB(Bb, ldb, 1, tid, bs0 + B_WORDS * 4); CP_COMMIT;
#pragma unroll
    for (int kt = 0; kt < 8; kt++){
        int cur = kt % 3;
        if (kt < 7){ CP_WAIT1; } else { CP_WAIT0; }
        __syncthreads();
        compute_tile(As + cur * A_WORDS, Bs + cur * B_WORDS, acc, wm, wn, gq, tg);
        if (kt < 6){
            int nx = (kt + 2) % 3;
            cpA(Ab, lda, kt + 2, tid, as0 + (unsigned)(nx * A_WORDS * 4));
            cpB(Bb, ldb, kt + 2, tid, bs0 + (unsigned)(nx * B_WORDS * 4));
            CP_COMMIT;
        }
    }
}

// ---------------- K6: sim via tf32 MMA, full async ----------------
__global__ void __launch_bounds__(256)
k_simmma(const float* __restrict__ qb, const float* __restrict__ kb,
         const float* __restrict__ invq, const float* __restrict__ invk,
         const float* __restrict__ ls, const float* __restrict__ biasb,
         float* __restrict__ simb){
    extern __shared__ unsigned smu[];
    unsigned* As  = smu;                 // 3*4608
    unsigned* BsT = smu + 3 * A_WORDS;   // 3*4608
    unsigned as0 = (unsigned)__cvta_generic_to_shared(As);
    unsigned bs0 = (unsigned)__cvta_generic_to_shared(BsT);
    int tid = threadIdx.x;
    int bz = blockIdx.z;
    int b = bz >> 2, h = bz & 3;
    const float* qbase = qb + (long)b * NC * LP + h * DH + (long)blockIdx.y * 128 * LP;
    const float* kbase = kb + (long)b * NC * LP + h * DH + (long)blockIdx.x * 128 * LP;

    int lane = tid & 31, w = tid >> 5, wm = w & 1, wn = w >> 1;
    int gq = lane >> 2, tg = lane & 3;

    float acc[4][4][4];
#pragma unroll
    for (int mt = 0; mt < 4; mt++)
#pragma unroll
        for (int nt = 0; nt < 4; nt++)
#pragma unroll
            for (int q = 0; q < 4; q++) acc[mt][nt][q] = 0.f;

    cpA(qbase, LP, 0, tid, as0); cpA(kbase, LP, 0, tid, bs0); CP_COMMIT;
    cpA(qbase, LP, 1, tid, as0 + A_WORDS * 4); cpA(kbase, LP, 1, tid, bs0 + A_WORDS * 4); CP_COMMIT;
#pragma unroll
    for (int kt = 0; kt < 8; kt++){
        int cur = kt % 3;
        if (kt < 7){ CP_WAIT1; } else { CP_WAIT0; }
        __syncthreads();
        {
            const unsigned* Ac = As + cur * A_WORDS;
            const unsigned* Bc = BsT + cur * A_WORDS;
#pragma unroll
            for (int ks = 0; ks < 4; ks++){
                unsigned af[4][4], bf[4][2];
                int c = ks * 8 + tg;
#pragma unroll
                for (int mt = 0; mt < 4; mt++){
                    int r = wm * 64 + mt * 16 + gq;
                    af[mt][0] = Ac[r * 36 + c];
                    af[mt][1] = Ac[(r + 8) * 36 + c];
                    af[mt][2] = Ac[r * 36 + c + 4];
                    af[mt][3] = Ac[(r + 8) * 36 + c + 4];
                }
#pragma unroll
                for (int nt = 0; nt < 4; nt++){
                    int cc = wn * 32 + nt * 8 + gq;
                    bf[nt][0] = Bc[cc * 36 + c];
                    bf[nt][1] = Bc[cc * 36 + c + 4];
                }
#pragma unroll
                for (int mt = 0; mt < 4; mt++)
#pragma unroll
                    for (int nt = 0; nt < 4; nt++)
                        mma8(acc[mt][nt], af[mt][0], af[mt][1], af[mt][2], af[mt][3],
                             bf[nt][0], bf[nt][1]);
            }
        }
        if (kt < 6){
            int nx = (kt + 2) % 3;
            cpA(qbase, LP, kt + 2, tid, as0 + (unsigned)(nx * A_WORDS * 4));
            cpA(kbase, LP, kt + 2, tid, bs0 + (unsigned)(nx * A_WORDS * 4));
            CP_COMMIT;
        }
    }

    float scale = expf(fminf(ls[h], 4.6051702f));
    int c0 = blockIdx.y * 128, e0 = blockIdx.x * 128;
    float* Cp = simb + (long)bz * 65536;
#pragma unroll
    for (int mt = 0; mt < 4; mt++){
        int rA = c0 + wm * 64 + mt * 16 + gq, rB = rA + 8;
        float iqA = invq[bz * 256 + rA] * scale;
        float iqB = invq[bz * 256 + rB] * scale;
#pragma unroll
        for (int nt = 0; nt < 4; nt++){
            int col = e0 + wn * 32 + nt * 8 + tg * 2;
            float ik0 = invk[bz * 256 + col], ik1 = invk[bz * 256 + col + 1];
            const float* bb = biasb + h * 65536;
            float2 o0 = make_float2(acc[mt][nt][0] * iqA * ik0 + bb[rA * 256 + col],
                                    acc[mt][nt][1] * iqA * ik1 + bb[rA * 256 + col + 1]);
            float2 o1 = make_float2(acc[mt][nt][2] * iqB * ik0 + bb[rB * 256 + col],
                                    acc[mt][nt][3] * iqB * ik1 + bb[rB * 256 + col + 1]);
            *(float2*)&Cp[(long)rA * 256 + col] = o0;
            *(float2*)&Cp[(long)rB * 256 + col] = o1;
        }
    }
}

// ---------------- K8: msim = proj @ sim  per (b,h), rounded output ----------------
__global__ void __launch_bounds__(256)
k_projsim(const float* __restrict__ proj, const float* __restrict__ simb,
          float* __restrict__ msim){
    extern __shared__ unsigned smu[];
    unsigned* As = smu;
    unsigned* Bs = smu + 3 * A_WORDS;
    unsigned as0 = (unsigned)__cvta_generic_to_shared(As);
    unsigned bs0 = (unsigned)__cvta_generic_to_shared(Bs);
    int tid = threadIdx.x;
    int bz = blockIdx.z;
    const float* Ab = proj + (long)blockIdx.y * 128 * 256;
    const float* Bb = simb + (long)bz * 65536 + blockIdx.x * 128;
    float* C = msim + (long)bz * 65536;

    float acc[4][4][4];
#pragma unroll
    for (int mt = 0; mt < 4; mt++)
#pragma unroll
        for (int nt = 0; nt < 4; nt++)
#pragma unroll
            for (int q = 0; q < 4; q++) acc[mt][nt][q] = 0.f;

    gemm_async(Ab, 256, Bb, 256, As, Bs, as0, bs0, acc, tid);

    int lane = tid & 31;
    int w = tid >> 5, wm = w & 1, wn = w >> 1;
    int gq = lane >> 2, tg = lane & 3;
    int m0 = blockIdx.y * 128 + wm * 64;
    int n0 = blockIdx.x * 128 + wn * 32;
#pragma unroll
    for (int mt = 0; mt < 4; mt++){
        int rA = m0 + mt * 16 + gq;
#pragma unroll
        for (int nt = 0; nt < 4; nt++){
            int col = n0 + nt * 8 + tg * 2;
            *(float2*)&C[(long)rA * 256 + col] =
                make_float2(roundtf(acc[mt][nt][0]), roundtf(acc[mt][nt][1]));
            *(float2*)&C[(long)(rA + 8) * 256 + col] =
                make_float2(roundtf(acc[mt][nt][2]), roundtf(acc[mt][nt][3]));
        }
    }
}

// ---------------- K9: out = gelu(msim_bh@vh + pb)*bn + relu(sc@x + scb) ----------------
__global__ void __launch_bounds__(256)
k_fused(const float* __restrict__ msim, const float* __restrict__ vbuf,
        const float* __restrict__ scw, const float* __restrict__ xbuf,
        float* __restrict__ Cg,
        const float* __restrict__ pb, const float* __restrict__ gam,
        const float* __restrict__ bet, const float* __restrict__ scb){
    extern __shared__ unsigned smu[];
    unsigned* As = smu;                      // 3 * 4608
    unsigned* Bs = smu + 3 * A_WORDS;        // 3 * 4352
    unsigned as0 = (unsigned)__cvta_generic_to_shared(As);
    unsigned bs0 = (unsigned)__cvta_generic_to_shared(Bs);
    int tid = threadIdx.x;
    int b = blockIdx.z;
    int h = blockIdx.x >> 5;
    const float* Ab = msim + ((long)(b * NHH + h)) * 65536 + (long)blockIdx.y * 128 * 256;
    const float* Bb = vbuf + (long)b * NC * HWSZ + blockIdx.x * 128;
    float* C = Cg + (long)b * NC * HWSZ;

    float acc[4][4][4];
#pragma unroll
    for (int mt = 0; mt < 4; mt++)
#pragma unroll
        for (int nt = 0; nt < 4; nt++)
#pragma unroll
            for (int q = 0; q < 4; q++) acc[mt][nt][q] = 0.f;

    gemm_async(Ab, 256, Bb, HWSZ, As, Bs, as0, bs0, acc, tid);

    int lane = tid & 31;
    int w = tid >> 5, wm = w & 1, wn = w >> 1;
    int gq = lane >> 2, tg = lane & 3;
    int m0 = blockIdx.y * 128 + wm * 64;
    long n0 = (long)blockIdx.x * 128 + wn * 32;

    const float BNS = 0.9999950000374998f;   // 1/sqrt(1+1e-5)
    const float ISQ2 = 0.70710678118654752f;
    float res[4][4][4];
#pragma unroll
    for (int mt = 0; mt < 4; mt++){
        int rA = m0 + mt * 16 + gq, rB = rA + 8;
        float pbA = pb[rA], pbB = pb[rB];
        float gaA = gam[rA] * BNS, gaB = gam[rB] * BNS;
        float beA = bet[rA], beB = bet[rB];
#pragma unroll
        for (int nt = 0; nt < 4; nt++){
            float z;
            z = acc[mt][nt][0] + pbA; res[mt][nt][0] = 0.5f*z*(1.f+erff(z*ISQ2))*gaA + beA;
            z = acc[mt][nt][1] + pbA; res[mt][nt][1] = 0.5f*z*(1.f+erff(z*ISQ2))*gaA + beA;
            z = acc[mt][nt][2] + pbB; res[mt][nt][2] = 0.5f*z*(1.f+erff(z*ISQ2))*gaB + beB;
            z = acc[mt][nt][3] + pbB; res[mt][nt][3] = 0.5f*z*(1.f+erff(z*ISQ2))*gaB + beB;
        }
    }
#pragma unroll
    for (int mt = 0; mt < 4; mt++)
#pragma unroll
        for (int nt = 0; nt < 4; nt++)
#pragma unroll
            for (int q = 0; q < 4; q++) acc[mt][nt][q] = 0.f;
    __syncthreads();

    gemm_async(scw + (long)blockIdx.y * 128 * 256, 256,
               xbuf + (long)b * NC * HWSZ + blockIdx.x * 128, HWSZ,
               As, Bs, as0, bs0, acc, tid);
#pragma unroll
    for (int mt = 0; mt < 4; mt++){
        int rA = m0 + mt * 16 + gq, rB = rA + 8;
        float sA = scb[rA], sB = scb[rB];
#pragma unroll
        for (int nt = 0; nt < 4; nt++){
            long col = n0 + nt * 8 + tg * 2;
            float2 o0 = make_float2(res[mt][nt][0] + fmaxf(acc[mt][nt][0] + sA, 0.f),
                                    res[mt][nt][1] + fmaxf(acc[mt][nt][1] + sA, 0.f));
            float2 o1 = make_float2(res[mt][nt][2] + fmaxf(acc[mt][nt][2] + sB, 0.f),
                                    res[mt][nt][3] + fmaxf(acc[mt][nt][3] + sB, 0.f));
            *(float2*)&C[(long)rA * HWSZ + col] = o0;
            *(float2*)&C[(long)rB * HWSZ + col] = o1;
        }
    }
}

// ---------------- launch ----------------
extern "C" void kernel_launch(void* const* d_in, const int* in_sizes, int n_in,
                              void* d_out, int out_size){
    const float* x        = (const float*)d_in[0];
    const float* sc_w     = (const float*)d_in[1];
    const float* sc_b     = (const float*)d_in[2];
    const float* q_w      = (const float*)d_in[3];
    const float* q_b      = (const float*)d_in[4];
    const float* k_w      = (const float*)d_in[5];
    const float* k_b      = (const float*)d_in[6];
    const float* v_dw_w   = (const float*)d_in[7];
    const float* v_dw_b   = (const float*)d_in[8];
    const float* v_pw_w   = (const float*)d_in[9];
    const float* v_pw_b   = (const float*)d_in[10];
    const float* logit_sc = (const float*)d_in[11];
    const float* cpb_w1   = (const float*)d_in[12];
    const float* cpb_b1   = (const float*)d_in[13];
    const float* cpb_w2   = (const float*)d_in[14];
    const float* proj_w   = (const float*)d_in[15];
    const float* proj_b   = (const float*)d_in[16];
    const float* bn_gamma = (const float*)d_in[17];
    const float* bn_beta  = (const float*)d_in[18];
    float* out = (float*)d_out;

    float *xp, *qb, *kb, *vb, *sim, *msim, *biasb, *invq, *invk, *projw, *scw;
    cudaGetSymbolAddress((void**)&xp,   g_xp);
    cudaGetSymbolAddress((void**)&qb,   g_q);
    cudaGetSymbolAddress((void**)&kb,   g_k);
    cudaGetSymbolAddress((void**)&vb,   g_v);
    cudaGetSymbolAddress((void**)&sim,  g_sim);
    cudaGetSymbolAddress((void**)&msim, g_msim);
    cudaGetSymbolAddress((void**)&biasb,g_bias);
    cudaGetSymbolAddress((void**)&invq, g_invq);
    cudaGetSymbolAddress((void**)&invk, g_invk);
    cudaGetSymbolAddress((void**)&projw,g_projw);
    cudaGetSymbolAddress((void**)&scw,  g_scw);

    const int dwpw_smem  = (32768 + 16640 + 4352) * 4;   // 215040
    const int sim_smem   = 6 * A_WORDS * 4;              // 110592
    const int gem_smem   = 3 * (A_WORDS + B_WORDS) * 4;  // 107520
    cudaFuncSetAttribute(k_dwpw,    cudaFuncAttributeMaxDynamicSharedMemorySize, dwpw_smem);
    cudaFuncSetAttribute(k_simmma,  cudaFuncAttributeMaxDynamicSharedMemorySize, sim_smem);
    cudaFuncSetAttribute(k_projsim, cudaFuncAttributeMaxDynamicSharedMemorySize, gem_smem);
    cudaFuncSetAttribute(k_fused,   cudaFuncAttributeMaxDynamicSharedMemorySize, gem_smem);

    // 1. maxpool 4x4  x -> xp
    k_maxpool<<<(NB*NC*LP)/256, 256>>>(x, xp);
    // 2/3. q,k grouped pw on pooled (outputs rounded to tf32)
    k_grouped_pw<<<dim3(LP/128, NG, NB), 128>>>(xp, q_w, q_b, qb, LP);
    k_grouped_pw<<<dim3(LP/128, NG, NB), 128>>>(xp, k_w, k_b, kb, LP);
    // 4. fused dw3x3+relu+pw(mma): x -> v (chunked cp.async)  [profiled launch]
    k_dwpw<<<dim3(HWSZ/256, NG, NB), 256, dwpw_smem>>>(x, v_dw_w, v_dw_b, v_pw_w, v_pw_b, vb);
    // 5. inverse row norms
    k_rownorm<<<2048, 256>>>(qb, kb, invq, invk);
    // 6. round weights to tf32
    k_roundw<<<256, 256>>>(proj_w, sc_w, projw, scw);
    // 7. CPB bias table
    k_cpb<<<256, 256>>>(cpb_w1, cpb_b1, cpb_w2, biasb);
    // 8. sim GEMM (tf32 mma, full async) + scale + bias
    k_simmma<<<dim3(2, 2, NB*NHH), 256, sim_smem>>>(qb, kb, invq, invk, logit_sc, biasb, sim);
    // 9. double softmax (warp per row, rounded output)
    k_dsoftmax<<<1024, 256>>>(sim);
    // 10. msim = proj @ sim per (b,h)
    k_projsim<<<dim3(2, 2, NB*NHH), 256, gem_smem>>>(projw, sim, msim);
    // 11. out = gelu(msim@vh + pb)*bn + relu(sc@x + scb)
    k_fused<<<dim3(HWSZ/128, 2, NB), 256, gem_smem>>>(msim, vb, scw, x, out,
                                                      proj_b, bn_gamma, bn_beta, sc_b);
}

// round 9
// speedup vs baseline: 1.5101x; 1.5101x over previous
#include <cuda_runtime.h>
#include <math.h>

// ---------------- problem constants ----------------
#define NB   8
#define NC   256
#define NG   4
#define CG   64
#define NHH  4
#define WW   128
#define HWSZ 16384        // 128*128
#define LP   1024         // pooled spatial (32*32)
#define DH   256          // LP/NH
#define DV   4096         // HW/NH

// ---------------- scratch ----------------
__device__ float g_xp [NB*NC*LP];
__device__ float g_q  [NB*NC*LP];
__device__ float g_k  [NB*NC*LP];
__device__ float g_v  [NB*NC*HWSZ];
__device__ float g_sim[NB*NHH*256*256];
__device__ float g_msim[NB*NHH*256*256];
__device__ float g_bias[NHH*256*256];
__device__ float g_invq[NB*NHH*256];
__device__ float g_invk[NB*NHH*256];

// ---------------- helpers ----------------
__device__ __forceinline__ float warpRedSum(float v){
#pragma unroll
    for (int o = 16; o > 0; o >>= 1) v += __shfl_xor_sync(0xffffffffu, v, o);
    return v;
}
__device__ __forceinline__ float warpRedMax(float v){
#pragma unroll
    for (int o = 16; o > 0; o >>= 1) v = fmaxf(v, __shfl_xor_sync(0xffffffffu, v, o));
    return v;
}
__device__ __forceinline__ float warpRedMin(float v){
#pragma unroll
    for (int o = 16; o > 0; o >>= 1) v = fminf(v, __shfl_xor_sync(0xffffffffu, v, o));
    return v;
}
__device__ __forceinline__ unsigned f2tf(float f){
    unsigned u; asm("cvt.rna.tf32.f32 %0, %1;" : "=r"(u) : "f"(f)); return u;
}
__device__ __forceinline__ void mma8(float* c, unsigned a0, unsigned a1, unsigned a2, unsigned a3,
                                     unsigned b0, unsigned b1){
    asm volatile("mma.sync.aligned.m16n8k8.row.col.f32.tf32.tf32.f32 "
                 "{%0,%1,%2,%3},{%4,%5,%6,%7},{%8,%9},{%0,%1,%2,%3};"
                 : "+f"(c[0]), "+f"(c[1]), "+f"(c[2]), "+f"(c[3])
                 : "r"(a0), "r"(a1), "r"(a2), "r"(a3), "r"(b0), "r"(b1));
}
#define CP_ASYNC16(saddr, gptr) \
    asm volatile("cp.async.cg.shared.global [%0], [%1], 16;" :: "r"(saddr), "l"(gptr))
#define CP_COMMIT  asm volatile("cp.async.commit_group;")
#define CP_WAIT0   asm volatile("cp.async.wait_group 0;")

// ---------------- K1: 4x4 maxpool ----------------
__global__ void k_maxpool(const float* __restrict__ xin, float* __restrict__ out){
    int idx = blockIdx.x * 256 + threadIdx.x;
    int pp = idx & 1023;
    int bc = idx >> 10;
    int ph = pp >> 5, pw = pp & 31;
    const float* xp = xin + (long)bc * HWSZ + (ph * 4) * WW + pw * 4;
    float m = -3.4e38f;
#pragma unroll
    for (int i = 0; i < 4; i++)
#pragma unroll
        for (int j = 0; j < 4; j++)
            m = fmaxf(m, xp[i * WW + j]);
    out[idx] = m;
}

// ---------------- K2: grouped 1x1 pw conv (pooled q/k path, small) ----------------
__global__ void k_grouped_pw(const float* __restrict__ in, const float* __restrict__ w,
                             const float* __restrict__ bias, float* __restrict__ out, int L){
    __shared__ float wsT[64 * 64];
    __shared__ float xs[64][128];
    int g = blockIdx.y, b = blockIdx.z;
    int l0 = blockIdx.x * 128;
    int t = threadIdx.x;
    for (int idx = t; idx < 4096; idx += 128){
        int i = idx >> 6, j = idx & 63;
        wsT[j * 64 + i] = w[g * 4096 + idx];
    }
    const float* ip = in + ((long)(b * NC + g * CG)) * L + l0;
#pragma unroll 8
    for (int j = 0; j < 64; j++) xs[j][t] = ip[(long)j * L + t];
    __syncthreads();
    float acc[64];
#pragma unroll
    for (int i = 0; i < 64; i++) acc[i] = 0.f;
#pragma unroll 4
    for (int j = 0; j < 64; j++){
        float xv = xs[j][t];
        const float4* wr = (const float4*)(wsT + j * 64);
#pragma unroll
        for (int i4 = 0; i4 < 16; i4++){
            float4 wv = wr[i4];
            acc[i4*4+0] += wv.x * xv;
            acc[i4*4+1] += wv.y * xv;
            acc[i4*4+2] += wv.z * xv;
            acc[i4*4+3] += wv.w * xv;
        }
    }
    float* op = out + ((long)(b * NC + g * CG)) * L + l0;
#pragma unroll 8
    for (int i = 0; i < 64; i++)
        op[(long)i * L + t] = acc[i] + bias[g * CG + i];
}

// ---------------- K3: fused dw3x3+relu (FFMA) + grouped pw (tf32 mma) ----------------
__global__ void __launch_bounds__(256)
k_dwpw(const float* __restrict__ x, const float* __restrict__ dw_w,
       const float* __restrict__ dw_b, const float* __restrict__ pw_w,
       const float* __restrict__ pw_b, float* __restrict__ vout){
    extern __shared__ float sm[];
    float*    xs  = sm;                        // 32768
    unsigned* Bs  = (unsigned*)(sm + 32768);   // 64*260 = 16640
    unsigned* Asw = Bs + 16640;                // 64*68 = 4352
    __shared__ float sdw[576];
    __shared__ float sdb[64];

    int g = blockIdx.y, b = blockIdx.z;
    int p0 = blockIdx.x * 256;
    int t = threadIdx.x;
    int y0 = p0 >> 7;
    const float* xb = x + ((long)(b * NC + g * CG)) * HWSZ;

    for (int idx = t; idx < 4096; idx += 256){
        int i = idx >> 6, j = idx & 63;
        Asw[i * 68 + j] = f2tf(pw_w[g * 4096 + idx]);
    }
    for (int idx = t; idx < 576; idx += 256) sdw[idx] = dw_w[g * 576 + idx];
    if (t < 64) sdb[t] = dw_b[g * 64 + t];

#pragma unroll
    for (int i = 0; i < 32; i++){
        int vid = t + i * 256;
        int c = vid >> 7;
        int rem = vid & 127;
        int ry = rem >> 5, col4 = (rem & 31) * 4;
        int row = y0 - 1 + ry;
        float4 v4 = make_float4(0.f, 0.f, 0.f, 0.f);
        if (row >= 0 && row <= 127)
            v4 = *(const float4*)(xb + (long)c * HWSZ + row * 128 + col4);
        *(float4*)&xs[(c * 4 + ry) * 128 + col4] = v4;
    }
    __syncthreads();

    int ly = 1 + (t >> 7);
    int xc = t & 127;
#pragma unroll 2
    for (int c = 0; c < 64; c++){
        float s = sdb[c];
        const float* xcb = xs + c * 512;
#pragma unroll
        for (int dy = 0; dy < 3; dy++){
            const float* xr = xcb + (ly + dy - 1) * 128;
#pragma unroll
            for (int dx = 0; dx < 3; dx++){
                int xx = xc + dx - 1;
                if (xx >= 0 && xx < 128) s += xr[xx] * sdw[c * 9 + dy * 3 + dx];
            }
        }
        Bs[c * 260 + t] = f2tf(fmaxf(s, 0.f));
    }
    __syncthreads();

    int lane = t & 31, w = t >> 5, wm = w & 1, wn = w >> 1;
    int gq = lane >> 2, tg = lane & 3;
    float acc[2][8][4];
#pragma unroll
    for (int mt = 0; mt < 2; mt++)
#pragma unroll
        for (int nt = 0; nt < 8; nt++)
#pragma unroll
            for (int q = 0; q < 4; q++) acc[mt][nt][q] = 0.f;

#pragma unroll
    for (int ks = 0; ks < 8; ks++){
        unsigned af[2][4], bf[8][2];
        int c = ks * 8 + tg;
#pragma unroll
        for (int mt = 0; mt < 2; mt++){
            int r = wm * 32 + mt * 16 + gq;
            af[mt][0] = Asw[r * 68 + c];
            af[mt][1] = Asw[(r + 8) * 68 + c];
            af[mt][2] = Asw[r * 68 + c + 4];
            af[mt][3] = Asw[(r + 8) * 68 + c + 4];
        }
#pragma unroll
        for (int nt = 0; nt < 8; nt++){
            int cc = wn * 64 + nt * 8 + gq;
            bf[nt][0] = Bs[c * 260 + cc];
            bf[nt][1] = Bs[(c + 4) * 260 + cc];
        }
#pragma unroll
        for (int mt = 0; mt < 2; mt++)
#pragma unroll
            for (int nt = 0; nt < 8; nt++)
                mma8(acc[mt][nt], af[mt][0], af[mt][1], af[mt][2], af[mt][3],
                     bf[nt][0], bf[nt][1]);
    }

#pragma unroll
    for (int mt = 0; mt < 2; mt++){
        int rA = wm * 32 + mt * 16 + gq, rB = rA + 8;
        float bA = pw_b[g * 64 + rA], bB = pw_b[g * 64 + rB];
        float* oA = vout + ((long)(b * NC + g * 64 + rA)) * HWSZ + p0;
        float* oB = vout + ((long)(b * NC + g * 64 + rB)) * HWSZ + p0;
#pragma unroll
        for (int nt = 0; nt < 8; nt++){
            int col = wn * 64 + nt * 8 + tg * 2;
            *(float2*)&oA[col] = make_float2(acc[mt][nt][0] + bA, acc[mt][nt][1] + bA);
            *(float2*)&oB[col] = make_float2(acc[mt][nt][2] + bB, acc[mt][nt][3] + bB);
        }
    }
}

// ---------------- K4: row inverse norms of q,k heads ----------------
__global__ void k_rownorm(const float* __restrict__ q, const float* __restrict__ k,
                          float* __restrict__ invq, float* __restrict__ invk){
    int gw = (blockIdx.x * blockDim.x + threadIdx.x) >> 5;
    int lane = threadIdx.x & 31;
    int sel = gw >> 13;
    int r = gw & 8191;
    int b = r >> 10; int rem = r & 1023; int h = rem >> 8; int c = rem & 255;
    const float* src = (sel ? k : q) + (long)b * NC * LP + (long)c * LP + h * DH;
    float s = 0.f;
#pragma unroll
    for (int d = lane; d < DH; d += 32){ float v = src[d]; s += v * v; }
    s = warpRedSum(s);
    if (lane == 0){
        float inv = 1.f / fmaxf(sqrtf(s), 1e-12f);
        (sel ? invk : invq)[(b * NHH + h) * 256 + c] = inv;
    }
}

// ---------------- K5: CPB relative position bias ----------------
__global__ void k_cpb(const float* __restrict__ w1, const float* __restrict__ b1,
                      const float* __restrict__ w2, float* __restrict__ biasb){
    __shared__ float s1[64], sb1[64], s2[256];
    int t = threadIdx.x;
    if (t < 64){ s1[t] = w1[t]; sb1[t] = b1[t]; }
    s2[t] = w2[t];
    __syncthreads();
    int idx = blockIdx.x * 256 + t;
    int i = idx >> 8, j = idx & 255;
    float coords = (float)(j - i);
    float rel = coords * (8.0f / 255.0f);
    float sg = (rel > 0.f) ? 1.f : ((rel < 0.f) ? -1.f : 0.f);
    float f = sg * log2f(fabsf(rel) + 1.f) * (1.f / 3.f);
    float o0 = 0.f, o1 = 0.f, o2 = 0.f, o3 = 0.f;
#pragma unroll 8
    for (int h = 0; h < 64; h++){
        float hv = fmaxf(f * s1[h] + sb1[h], 0.f);
        o0 += hv * s2[h * 4 + 0];
        o1 += hv * s2[h * 4 + 1];
        o2 += hv * s2[h * 4 + 2];
        o3 += hv * s2[h * 4 + 3];
    }
    biasb[0 * 65536 + idx] = 1.f / (1.f + expf(-o0));
    biasb[1 * 65536 + idx] = 1.f / (1.f + expf(-o1));
    biasb[2 * 65536 + idx] = 1.f / (1.f + expf(-o2));
    biasb[3 * 65536 + idx] = 1.f / (1.f + expf(-o3));
}

// ---------------- K7: double softmax, warp per row (no barriers) ----------------
__global__ void k_dsoftmax(float* __restrict__ simb){
    int row = blockIdx.x * 8 + (threadIdx.x >> 5);
    int lane = threadIdx.x & 31;
    float* p = simb + (long)row * 256;
    float v[8];
#pragma unroll
    for (int j = 0; j < 8; j++) v[j] = p[lane + 32 * j];
    float m = v[0];
#pragma unroll
    for (int j = 1; j < 8; j++) m = fmaxf(m, v[j]);
    m = warpRedMax(m);
    float s = 0.f;
#pragma unroll
    for (int j = 0; j < 8; j++){ v[j] = expf(v[j] - m); s += v[j]; }
    s = warpRedSum(s);
    float inv = 1.f / s;
    float mn = v[0];
#pragma unroll
    for (int j = 1; j < 8; j++) mn = fminf(mn, v[j]);
    mn = warpRedMin(mn);
    // softmax(1-p) == softmax(-p); shift by row-min of p for stability
    float e2[8]; float s2 = 0.f;
#pragma unroll
    for (int j = 0; j < 8; j++){ e2[j] = expf((mn - v[j]) * inv); s2 += e2[j]; }
    s2 = warpRedSum(s2);
    float i2 = 1.f / s2;
#pragma unroll
    for (int j = 0; j < 8; j++) p[lane + 32 * j] = e2[j] * i2;
}

// ---------------- shared tf32 tile sizes ----------------
#define A_WORDS 4608   // 128*36
#define B_WORDS 4352   // 32*136

// ---- A-side register staging (rna cvt) ----
__device__ __forceinline__ void ldA(const float* __restrict__ Ab, long lda, int kt, int tid, float4* ar){
#pragma unroll
    for (int i = 0; i < 4; i++){
        int vid = tid + i * 256;
        int r = vid >> 3, c4 = (vid & 7) << 2;
        ar[i] = *(const float4*)(Ab + (long)r * lda + kt * 32 + c4);
    }
}
__device__ __forceinline__ void stA(unsigned* As, int tid, const float4* ar){
#pragma unroll
    for (int i = 0; i < 4; i++){
        int vid = tid + i * 256;
        int r = vid >> 3, c4 = (vid & 7) << 2;
        uint4 ua; ua.x = f2tf(ar[i].x); ua.y = f2tf(ar[i].y); ua.z = f2tf(ar[i].z); ua.w = f2tf(ar[i].w);
        *(uint4*)&As[r * 36 + c4] = ua;
    }
}
// ---- B-side (row-major [k][n]) ----
__device__ __forceinline__ void ldB(const float* __restrict__ Bb, long ldb, int kt, int tid, float4* br){
#pragma unroll
    for (int i = 0; i < 4; i++){
        int vid = tid + i * 256;
        int kr = vid >> 5, n4 = (vid & 31) << 2;
        br[i] = *(const float4*)(Bb + (long)(kt * 32 + kr) * ldb + n4);
    }
}
__device__ __forceinline__ void stB(unsigned* Bs, int tid, const float4* br){
#pragma unroll
    for (int i = 0; i < 4; i++){
        int vid = tid + i * 256;
        int kr = vid >> 5, n4 = (vid & 31) << 2;
        uint4 ub; ub.x = f2tf(br[i].x); ub.y = f2tf(br[i].y); ub.z = f2tf(br[i].z); ub.w = f2tf(br[i].w);
        *(uint4*)&Bs[kr * 136 + n4] = ub;
    }
}
// ---- B-side cp.async (raw fp32 -> tf32 by truncation) ----
__device__ __forceinline__ void cpB(const float* __restrict__ Bb, long ldb, int kt, int tid,
                                    unsigned bs_u32){
#pragma unroll
    for (int i = 0; i < 4; i++){
        int vid = tid + i * 256;
        int kr = vid >> 5, n4 = (vid & 31) << 2;
        CP_ASYNC16(bs_u32 + (unsigned)((kr * 136 + n4) * 4),
                   Bb + (long)(kt * 32 + kr) * ldb + n4);
    }
}

__device__ __forceinline__ void compute_tile(const unsigned* As, const unsigned* Bs,
        float acc[4][4][4], int wm, int wn, int gq, int tg){
#pragma unroll
    for (int ks = 0; ks < 4; ks++){
        unsigned af[4][4], bf[4][2];
        int c = ks * 8 + tg;
#pragma unroll
        for (int mt = 0; mt < 4; mt++){
            int r = wm * 64 + mt * 16 + gq;
            af[mt][0] = As[r * 36 + c];
            af[mt][1] = As[(r + 8) * 36 + c];
            af[mt][2] = As[r * 36 + c + 4];
            af[mt][3] = As[(r + 8) * 36 + c + 4];
        }
#pragma unroll
        for (int nt = 0; nt < 4; nt++){
            int cc = wn * 32 + nt * 8 + gq;
            bf[nt][0] = Bs[c * 136 + cc];
            bf[nt][1] = Bs[(c + 4) * 136 + cc];
        }
#pragma unroll
        for (int mt = 0; mt < 4; mt++)
#pragma unroll
            for (int nt = 0; nt < 4; nt++)
                mma8(acc[mt][nt], af[mt][0], af[mt][1], af[mt][2], af[mt][3],
                     bf[nt][0], bf[nt][1]);
    }
}

// ---- register-staged double-buffered GEMM (projsim) ----
__device__ __forceinline__ void gemm_db(const float* __restrict__ Ab,
        const float* __restrict__ Bb, long ldb,
        unsigned* As, unsigned* Bs, float acc[4][4][4], int tid){
    int lane = tid & 31, w = tid >> 5, wm = w & 1, wn = w >> 1;
    int gq = lane >> 2, tg = lane & 3;
    float4 ar[4], br[4];
    ldA(Ab, 256, 0, tid, ar); ldB(Bb, ldb, 0, tid, br);
    stA(As, tid, ar); stB(Bs, tid, br);
    __syncthreads();
#pragma unroll
    for (int kt = 0; kt < 8; kt++){
        int cur = kt & 1;
        if (kt < 7){ ldA(Ab, 256, kt + 1, tid, ar); ldB(Bb, ldb, kt + 1, tid, br); }
        compute_tile(As + cur * A_WORDS, Bs + cur * B_WORDS, acc, wm, wn, gq, tg);
        if (kt < 7){ stA(As + (cur ^ 1) * A_WORDS, tid, ar); stB(Bs + (cur ^ 1) * B_WORDS, tid, br); }
        __syncthreads();
    }
}

// ---- mixed pipeline: A via regs+cvt, B via cp.async (k_fused) ----
__device__ __forceinline__ void gemm_mixed(const float* __restrict__ Ab,
        const float* __restrict__ Bb, long ldb,
        unsigned* As, unsigned* Bs, unsigned bs_u32, float acc[4][4][4], int tid){
    int lane = tid & 31, w = tid >> 5, wm = w & 1, wn = w >> 1;
    int gq = lane >> 2, tg = lane & 3;
    float4 ar[4];
    ldA(Ab, 256, 0, tid, ar);
    cpB(Bb, ldb, 0, tid, bs_u32);
    CP_COMMIT;
    stA(As, tid, ar);
    ldA(Ab, 256, 1, tid, ar);
    CP_WAIT0;
    __syncthreads();
#pragma unroll
    for (int kt = 0; kt < 8; kt++){
        int cur = kt & 1, nxt = cur ^ 1;
        if (kt < 7){
            cpB(Bb, ldb, kt + 1, tid, bs_u32 + (unsigned)(nxt * B_WORDS * 4));
            CP_COMMIT;
        }
        compute_tile(As + cur * A_WORDS, Bs + cur * B_WORDS, acc, wm, wn, gq, tg);
        if (kt < 7){
            stA(As + nxt * A_WORDS, tid, ar);
            if (kt < 6) ldA(Ab, 256, kt + 2, tid, ar);
            CP_WAIT0;
        }
        __syncthreads();
    }
}

// ---------------- K6: sim via tf32 MMA ----------------
__global__ void __launch_bounds__(256)
k_simmma(const float* __restrict__ qb, const float* __restrict__ kb,
         const float* __restrict__ invq, const float* __restrict__ invk,
         const float* __restrict__ ls, const float* __restrict__ biasb,
         float* __restrict__ simb){
    extern __shared__ unsigned smu[];
    unsigned* As  = smu;                 // 2*4608
    unsigned* BsT = smu + 2 * A_WORDS;   // 2*4608
    int tid = threadIdx.x;
    int bz = blockIdx.z;
    int b = bz >> 2, h = bz & 3;
    const float* qbase = qb + (long)b * NC * LP + h * DH + (long)blockIdx.y * 128 * LP;
    const float* kbase = kb + (long)b * NC * LP + h * DH + (long)blockIdx.x * 128 * LP;

    int lane = tid & 31, w = tid >> 5, wm = w & 1, wn = w >> 1;
    int gq = lane >> 2, tg = lane & 3;

    float acc[4][4][4];
#pragma unroll
    for (int mt = 0; mt < 4; mt++)
#pragma unroll
        for (int nt = 0; nt < 4; nt++)
#pragma unroll
            for (int q = 0; q < 4; q++) acc[mt][nt][q] = 0.f;

    float4 ar[4], br[4];
    ldA(qbase, LP, 0, tid, ar); ldA(kbase, LP, 0, tid, br);
    stA(As, tid, ar); stA(BsT, tid, br);
    __syncthreads();
#pragma unroll
    for (int kt = 0; kt < 8; kt++){
        int cur = kt & 1;
        if (kt < 7){ ldA(qbase, LP, kt + 1, tid, ar); ldA(kbase, LP, kt + 1, tid, br); }
        {
            const unsigned* Ac = As + cur * A_WORDS;
            const unsigned* Bc = BsT + cur * A_WORDS;
#pragma unroll
            for (int ks = 0; ks < 4; ks++){
                unsigned af[4][4], bf[4][2];
                int c = ks * 8 + tg;
#pragma unroll
                for (int mt = 0; mt < 4; mt++){
                    int r = wm * 64 + mt * 16 + gq;
                    af[mt][0] = Ac[r * 36 + c];
                    af[mt][1] = Ac[(r + 8) * 36 + c];
                    af[mt][2] = Ac[r * 36 + c + 4];
                    af[mt][3] = Ac[(r + 8) * 36 + c + 4];
                }
#pragma unroll
                for (int nt = 0; nt < 4; nt++){
                    int cc = wn * 32 + nt * 8 + gq;
                    bf[nt][0] = Bc[cc * 36 + c];
                    bf[nt][1] = Bc[cc * 36 + c + 4];
                }
#pragma unroll
                for (int mt = 0; mt < 4; mt++)
#pragma unroll
                    for (int nt = 0; nt < 4; nt++)
                        mma8(acc[mt][nt], af[mt][0], af[mt][1], af[mt][2], af[mt][3],
                             bf[nt][0], bf[nt][1]);
            }
        }
        if (kt < 7){ stA(As + (cur ^ 1) * A_WORDS, tid, ar); stA(BsT + (cur ^ 1) * A_WORDS, tid, br); }
        __syncthreads();
    }

    float scale = expf(fminf(ls[h], 4.6051702f));
    int c0 = blockIdx.y * 128, e0 = blockIdx.x * 128;
    float* Cp = simb + (long)bz * 65536;
#pragma unroll
    for (int mt = 0; mt < 4; mt++){
        int rA = c0 + wm * 64 + mt * 16 + gq, rB = rA + 8;
        float iqA = invq[bz * 256 + rA] * scale;
        float iqB = invq[bz * 256 + rB] * scale;
#pragma unroll
        for (int nt = 0; nt < 4; nt++){
            int col = e0 + wn * 32 + nt * 8 + tg * 2;
            float ik0 = invk[bz * 256 + col], ik1 = invk[bz * 256 + col + 1];
            const float* bb = biasb + h * 65536;
            float2 o0 = make_float2(acc[mt][nt][0] * iqA * ik0 + bb[rA * 256 + col],
                                    acc[mt][nt][1] * iqA * ik1 + bb[rA * 256 + col + 1]);
            float2 o1 = make_float2(acc[mt][nt][2] * iqB * ik0 + bb[rB * 256 + col],
                                    acc[mt][nt][3] * iqB * ik1 + bb[rB * 256 + col + 1]);
            *(float2*)&Cp[(long)rA * 256 + col] = o0;
            *(float2*)&Cp[(long)rB * 256 + col] = o1;
        }
    }
}

// ---------------- K8: msim = proj @ sim  per (b,h) ----------------
__global__ void __launch_bounds__(256)
k_projsim(const float* __restrict__ proj, const float* __restrict__ simb,
          float* __restrict__ msim){
    extern __shared__ unsigned smu[];
    unsigned* As = smu;
    unsigned* Bs = smu + 2 * A_WORDS;
    int tid = threadIdx.x;
    int bz = blockIdx.z;
    const float* Ab = proj + (long)blockIdx.y * 128 * 256;
    const float* Bb = simb + (long)bz * 65536 + blockIdx.x * 128;
    float* C = msim + (long)bz * 65536;

    float acc[4][4][4];
#pragma unroll
    for (int mt = 0; mt < 4; mt++)
#pragma unroll
        for (int nt = 0; nt < 4; nt++)
#pragma unroll
            for (int q = 0; q < 4; q++) acc[mt][nt][q] = 0.f;

    gemm_db(Ab, Bb, 256, As, Bs, acc, tid);

    int lane = tid & 31;
    int w = tid >> 5, wm = w & 1, wn = w >> 1;
    int gq = lane >> 2, tg = lane & 3;
    int m0 = blockIdx.y * 128 + wm * 64;
    int n0 = blockIdx.x * 128 + wn * 32;
#pragma unroll
    for (int mt = 0; mt < 4; mt++){
        int rA = m0 + mt * 16 + gq;
#pragma unroll
        for (int nt = 0; nt < 4; nt++){
            int col = n0 + nt * 8 + tg * 2;
            *(float2*)&C[(long)rA * 256 + col]       = make_float2(acc[mt][nt][0], acc[mt][nt][1]);
            *(float2*)&C[(long)(rA + 8) * 256 + col] = make_float2(acc[mt][nt][2], acc[mt][nt][3]);
        }
    }
}

// ---------------- K9: out = gelu(msim_bh@vh + pb)*bn + relu(sc@x + scb) ----------------
// grid (128, 2, 8). h = blockIdx.x / 32. 128x128 tiles, mixed cp.async pipeline.
__global__ void __launch_bounds__(256)
k_fused(const float* __restrict__ msim, const float* __restrict__ vbuf,
        const float* __restrict__ scw, const float* __restrict__ xbuf,
        float* __restrict__ Cg,
        const float* __restrict__ pb, const float* __restrict__ gam,
        const float* __restrict__ bet, const float* __restrict__ scb){
    extern __shared__ unsigned smu[];
    unsigned* As = smu;                      // 2 * 4608
    unsigned* Bs = smu + 2 * A_WORDS;        // 2 * 4352
    unsigned bs_u32 = (unsigned)__cvta_generic_to_shared(Bs);
    int tid = threadIdx.x;
    int b = blockIdx.z;
    int h = blockIdx.x >> 5;
    const float* A = msim + ((long)(b * NHH + h)) * 65536;
    const float* B = vbuf + (long)b * NC * HWSZ;
    float* C = Cg + (long)b * NC * HWSZ;

    const float* Ab = A + (long)blockIdx.y * 128 * 256;
    const float* Bb = B + blockIdx.x * 128;

    float acc[4][4][4];
#pragma unroll
    for (int mt = 0; mt < 4; mt++)
#pragma unroll
        for (int nt = 0; nt < 4; nt++)
#pragma unroll
            for (int q = 0; q < 4; q++) acc[mt][nt][q] = 0.f;

    gemm_mixed(Ab, Bb, HWSZ, As, Bs, bs_u32, acc, tid);

    int lane = tid & 31;
    int w = tid >> 5, wm = w & 1, wn = w >> 1;
    int gq = lane >> 2, tg = lane & 3;
    int m0 = blockIdx.y * 128 + wm * 64;
    long n0 = (long)blockIdx.x * 128 + wn * 32;

    const float BNS = 0.9999950000374998f;   // 1/sqrt(1+1e-5)
    const float ISQ2 = 0.70710678118654752f;
    float res[4][4][4];
#pragma unroll
    for (int mt = 0; mt < 4; mt++){
        int rA = m0 + mt * 16 + gq, rB = rA + 8;
        float pbA = pb[rA], pbB = pb[rB];
        float gaA = gam[rA] * BNS, gaB = gam[rB] * BNS;
        float beA = bet[rA], beB = bet[rB];
#pragma unroll
        for (int nt = 0; nt < 4; nt++){
            float z;
            z = acc[mt][nt][0] + pbA; res[mt][nt][0] = 0.5f*z*(1.f+erff(z*ISQ2))*gaA + beA;
            z = acc[mt][nt][1] + pbA; res[mt][nt][1] = 0.5f*z*(1.f+erff(z*ISQ2))*gaA + beA;
            z = acc[mt][nt][2] + pbB; res[mt][nt][2] = 0.5f*z*(1.f+erff(z*ISQ2))*gaB + beB;
            z = acc[mt][nt][3] + pbB; res[mt][nt][3] = 0.5f*z*(1.f+erff(z*ISQ2))*gaB + beB;
        }
    }
#pragma unroll
    for (int mt = 0; mt < 4; mt++)
#pragma unroll
        for (int nt = 0; nt < 4; nt++)
#pragma unroll
            for (int q = 0; q < 4; q++) acc[mt][nt][q] = 0.f;
    __syncthreads();

    gemm_mixed(scw + (long)blockIdx.y * 128 * 256,
               xbuf + (long)b * NC * HWSZ + blockIdx.x * 128,
               HWSZ, As, Bs, bs_u32, acc, tid);
#pragma unroll
    for (int mt = 0; mt < 4; mt++){
        int rA = m0 + mt * 16 + gq, rB = rA + 8;
        float sA = scb[rA], sB = scb[rB];
#pragma unroll
        for (int nt = 0; nt < 4; nt++){
            long col = n0 + nt * 8 + tg * 2;
            float2 o0 = make_float2(res[mt][nt][0] + fmaxf(acc[mt][nt][0] + sA, 0.f),
                                    res[mt][nt][1] + fmaxf(acc[mt][nt][1] + sA, 0.f));
            float2 o1 = make_float2(res[mt][nt][2] + fmaxf(acc[mt][nt][2] + sB, 0.f),
                                    res[mt][nt][3] + fmaxf(acc[mt][nt][3] + sB, 0.f));
            *(float2*)&C[(long)rA * HWSZ + col] = o0;
            *(float2*)&C[(long)rB * HWSZ + col] = o1;
        }
    }
}

// ---------------- launch ----------------
extern "C" void kernel_launch(void* const* d_in, const int* in_sizes, int n_in,
                              void* d_out, int out_size){
    const float* x        = (const float*)d_in[0];
    const float* sc_w     = (const float*)d_in[1];
    const float* sc_b     = (const float*)d_in[2];
    const float* q_w      = (const float*)d_in[3];
    const float* q_b      = (const float*)d_in[4];
    const float* k_w      = (const float*)d_in[5];
    const float* k_b      = (const float*)d_in[6];
    const float* v_dw_w   = (const float*)d_in[7];
    const float* v_dw_b   = (const float*)d_in[8];
    const float* v_pw_w   = (const float*)d_in[9];
    const float* v_pw_b   = (const float*)d_in[10];
    const float* logit_sc = (const float*)d_in[11];
    const float* cpb_w1   = (const float*)d_in[12];
    const float* cpb_b1   = (const float*)d_in[13];
    const float* cpb_w2   = (const float*)d_in[14];
    const float* proj_w   = (const float*)d_in[15];
    const float* proj_b   = (const float*)d_in[16];
    const float* bn_gamma = (const float*)d_in[17];
    const float* bn_beta  = (const float*)d_in[18];
    float* out = (float*)d_out;

    float *xp, *qb, *kb, *vb, *sim, *msim, *biasb, *invq, *invk;
    cudaGetSymbolAddress((void**)&xp,   g_xp);
    cudaGetSymbolAddress((void**)&qb,   g_q);
    cudaGetSymbolAddress((void**)&kb,   g_k);
    cudaGetSymbolAddress((void**)&vb,   g_v);
    cudaGetSymbolAddress((void**)&sim,  g_sim);
    cudaGetSymbolAddress((void**)&msim, g_msim);
    cudaGetSymbolAddress((void**)&biasb,g_bias);
    cudaGetSymbolAddress((void**)&invq, g_invq);
    cudaGetSymbolAddress((void**)&invk, g_invk);

    const int dwpw_smem  = (32768 + 16640 + 4352) * 4;             // 215040
    const int mma_smem   = 2 * (A_WORDS + B_WORDS) * 4;            // 71680
    const int sim_smem   = 4 * A_WORDS * 4;                        // 73728
    cudaFuncSetAttribute(k_dwpw,    cudaFuncAttributeMaxDynamicSharedMemorySize, dwpw_smem);
    cudaFuncSetAttribute(k_projsim, cudaFuncAttributeMaxDynamicSharedMemorySize, mma_smem);
    cudaFuncSetAttribute(k_fused,   cudaFuncAttributeMaxDynamicSharedMemorySize, mma_smem);
    cudaFuncSetAttribute(k_simmma,  cudaFuncAttributeMaxDynamicSharedMemorySize, sim_smem);

    // 1. maxpool 4x4  x -> xp
    k_maxpool<<<(NB*NC*LP)/256, 256>>>(x, xp);
    // 2/3. q,k grouped pw on pooled
    k_grouped_pw<<<dim3(LP/128, NG, NB), 128>>>(xp, q_w, q_b, qb, LP);
    k_grouped_pw<<<dim3(LP/128, NG, NB), 128>>>(xp, k_w, k_b, kb, LP);
    // 4. fused dw3x3+relu+pw(mma): x -> v  [profiled slot]
    k_dwpw<<<dim3(HWSZ/256, NG, NB), 256, dwpw_smem>>>(x, v_dw_w, v_dw_b, v_pw_w, v_pw_b, vb);
    // 5. inverse row norms
    k_rownorm<<<2048, 256>>>(qb, kb, invq, invk);
    // 6. CPB bias table
    k_cpb<<<256, 256>>>(cpb_w1, cpb_b1, cpb_w2, biasb);
    // 7. sim GEMM (tf32 mma) + scale + bias
    k_simmma<<<dim3(2, 2, NB*NHH), 256, sim_smem>>>(qb, kb, invq, invk, logit_sc, biasb, sim);
    // 8. double softmax (warp per row)
    k_dsoftmax<<<1024, 256>>>(sim);
    // 9. msim = proj @ sim per (b,h)
    k_projsim<<<dim3(2, 2, NB*NHH), 256, mma_smem>>>(proj_w, sim, msim);
    // 10. out = gelu(msim@vh + pb)*bn + relu(sc@x + scb)
    k_fused<<<dim3(HWSZ/128, 2, NB), 256, mma_smem>>>(msim, vb, sc_w, x, out,
                                                      proj_b, bn_gamma, bn_beta, sc_b);
}